// round 14
// baseline (speedup 1.0000x reference)
#include <cuda_runtime.h>
#include <cstdint>

#define EPS_BN 1e-5f
typedef unsigned long long u64;

static constexpr int NSM     = 148;
static constexpr int NPIPE   = 8;      // independent 64-thread pipelines per CTA
static constexpr int NBUF    = 4;
static constexpr int STAGE_B = 4096;   // 2 rows x 2048 B
static constexpr int NSTAGES = 24;     // 48 rows / 2

// ---------------- smem map (bytes) ----------------
static constexpr int OFF_W    = 0;        // 192 kq * 36 u64 = 55296
static constexpr int OFF_X    = 55296;    // 8 pipes * 4 bufs * 4096 = 131072
static constexpr int OFF_R1   = 186368;   // 8 * 512 f = 16384
static constexpr int OFF_RES  = 202752;   // 8 * 32 f = 1024
static constexpr int OFF_ROW  = 203776;   // 8 * 512 f = 16384
static constexpr int OFF_MBF  = 220160;   // 8 pipes * 4 = 256
static constexpr int OFF_MBE  = 220416;   // 256
static constexpr int OFF_T1   = 220672;
static constexpr int OFF_W2   = 220736;
static constexpr int OFF_T2   = 220992;
static constexpr int OFF_W3   = 221008;
static constexpr int OFF_B3   = 221024;
static constexpr int SMEM_BYTES = 221056;

// ---------------- helpers ----------------
__device__ __forceinline__ u64 pack2(float a, float b) {
    return ((u64)__float_as_uint(b) << 32) | (u64)__float_as_uint(a);
}
__device__ __forceinline__ void ffma2(u64& a, u64 x, u64 w) {
    asm("fma.rn.f32x2 %0, %1, %2, %0;" : "+l"(a) : "l"(x), "l"(w));
}
__device__ __forceinline__ u64 add2(u64 a, u64 b) {
    u64 r;
    asm("add.rn.f32x2 %0, %1, %2;" : "=l"(r) : "l"(a), "l"(b));
    return r;
}
__device__ __forceinline__ float hsum2(u64 a) {
    unsigned lo, hi;
    asm("mov.b64 {%0,%1}, %2;" : "=r"(lo), "=r"(hi) : "l"(a));
    return __uint_as_float(lo) + __uint_as_float(hi);
}
__device__ __forceinline__ void mbar_init(unsigned mb, unsigned cnt) {
    asm volatile("mbarrier.init.shared.b64 [%0], %1;" :: "r"(mb), "r"(cnt) : "memory");
}
__device__ __forceinline__ void mbar_wait_acq(unsigned mb, unsigned phase) {
    asm volatile(
        "{\n\t.reg .pred P;\n"
        "W%=:\n\t"
        "mbarrier.try_wait.parity.acquire.cta.shared::cta.b64 P, [%0], %1, 0x989680;\n\t"
        "@P bra D%=;\n\t"
        "bra W%=;\n"
        "D%=:\n\t}"
        :: "r"(mb), "r"(phase) : "memory");
}
__device__ __forceinline__ void mbar_wait_rlx(unsigned mb, unsigned phase) {
    asm volatile(
        "{\n\t.reg .pred P;\n"
        "W%=:\n\t"
        "mbarrier.try_wait.parity.relaxed.cta.shared::cta.b64 P, [%0], %1, 0x989680;\n\t"
        "@P bra D%=;\n\t"
        "bra W%=;\n"
        "D%=:\n\t}"
        :: "r"(mb), "r"(phase) : "memory");
}
__device__ __forceinline__ void mbar_arrive(unsigned mb) {
    asm volatile("mbarrier.arrive.shared.b64 _, [%0];" :: "r"(mb) : "memory");
}
__device__ __forceinline__ void barp(int id) {
    asm volatile("bar.sync %0, 64;" :: "r"(id) : "memory");
}
// one 4KB stage = 2 gmem rows of the strip
__device__ __forceinline__ void issue_stage(unsigned xs, const float* gin, int q, unsigned mb) {
    asm volatile("mbarrier.arrive.expect_tx.shared.b64 _, [%0], %1;"
                 :: "r"(mb), "r"(4096u) : "memory");
#pragma unroll
    for (int r = 0; r < 2; r++) {
        int rgg = q * 2 + r;   // 0..47
        const float* src = gin + (size_t)(rgg >> 4) * 262144 + (rgg & 15) * 512;
        asm volatile(
            "cp.async.bulk.shared::cluster.global.mbarrier::complete_tx::bytes [%0], [%1], %2, [%3];"
            :: "r"(xs + r * 2048), "l"(src), "r"(2048u), "r"(mb) : "memory");
    }
}
__device__ __forceinline__ void bulk_s2g(void* gdst, unsigned ssrc, unsigned bytes) {
    asm volatile("cp.async.bulk.global.shared::cta.bulk_group [%0], [%1], %2;"
                 :: "l"(gdst), "r"(ssrc), "r"(bytes) : "memory");
}

__global__ void __launch_bounds__(512, 1)
cnn_kernel(const float* __restrict__ in, float* __restrict__ out,
           const float* __restrict__ w1, const float* __restrict__ b1,
           const float* __restrict__ g1, const float* __restrict__ be1,
           const float* __restrict__ m1, const float* __restrict__ v1,
           const float* __restrict__ w2, const float* __restrict__ b2,
           const float* __restrict__ g2, const float* __restrict__ be2,
           const float* __restrict__ m2, const float* __restrict__ v2,
           const float* __restrict__ w3, const float* __restrict__ b3) {
    extern __shared__ char smem[];
    const unsigned sbase = (unsigned)__cvta_generic_to_shared(smem);

    const int t     = threadIdx.x;
    const int pipe  = t >> 6;          // 0..7, independent 64-thread pipeline
    const int tl    = t & 63;
    const int cg    = tl >> 5;         // warp in pipe = channel group (8 ch)
    const int lane  = t & 31;
    const int dxq   = lane & 3;
    const int pbase = lane >> 2;       // 0..7
    const int xoff  = pbase * 64 + dxq * 16;
    const int barid = 1 + pipe;

    u64*   wsm   = (u64*)(smem + OFF_W);
    float* r1    = (float*)(smem + OFF_R1)  + pipe * 512;
    float* res   = (float*)(smem + OFF_RES) + pipe * 32;
    float* rowb  = (float*)(smem + OFF_ROW) + pipe * 512;
    float* sh_t1 = (float*)(smem + OFF_T1);
    float* sh_w2 = (float*)(smem + OFF_W2);
    float* sh_t2 = (float*)(smem + OFF_T2);
    float* sh_w3 = (float*)(smem + OFF_W3);
    float* sh_b3 = (float*)(smem + OFF_B3);
    char*  xpb   = smem + OFF_X + pipe * (NBUF * STAGE_B);
    const unsigned mbf0 = sbase + OFF_MBF + pipe * NBUF * 8;
    const unsigned mbe0 = sbase + OFF_MBE + pipe * NBUF * 8;
    const unsigned xs0  = sbase + OFF_X + pipe * (NBUF * STAGE_B);

    const int P = blockIdx.x + NSM * pipe;   // strip id; 1184 pipes >= 1024 strips
    const bool active = (P < 1024);

    if (t == 0) {
#pragma unroll
        for (int i = 0; i < NPIPE * NBUF; i++) {
            mbar_init(sbase + OFF_MBF + i * 8, 1);
            mbar_init(sbase + OFF_MBE + i * 8, 2);   // one arrive per warp
        }
    }
    __syncthreads();

    const float* gin = in + (size_t)(P >> 5) * 786432 + (size_t)(P & 31) * 8192;
    if (active && tl == 0) {
#pragma unroll
        for (int g0 = 0; g0 < 3; g0++)   // prologue: 3-ahead steady state
            issue_stage(xs0 + g0 * STAGE_B, gin, g0, mbf0 + g0 * 8);
    }

    // ---- fold BN1 into conv1 weights (hides prefetch latency) ----
#pragma unroll
    for (int j = 0; j < 6; j++) {
        int idx = j * 512 + t;          // 0..3071
        int c = idx & 15, kq = idx >> 4;
        float s1 = __ldg(g1 + c) * rsqrtf(__ldg(v1 + c) + EPS_BN);
        float4 w = *(const float4*)(w1 + c * 768 + kq * 4);
        wsm[kq * 36 + c]      = pack2(w.x * s1, w.y * s1);
        wsm[kq * 36 + 16 + c] = pack2(w.z * s1, w.w * s1);
    }
    if (t < 16) {
        float s1 = __ldg(g1 + t) * rsqrtf(__ldg(v1 + t) + EPS_BN);
        sh_t1[t] = __ldg(b1 + t) * s1 + __ldg(be1 + t) - __ldg(m1 + t) * s1;
    }
    if (t < 64) {
        int o = t >> 4;
        float s2 = __ldg(g2 + o) * rsqrtf(__ldg(v2 + o) + EPS_BN);
        sh_w2[t] = __ldg(w2 + t) * s2;
    }
    if (t < 4) {
        float s2 = __ldg(g2 + t) * rsqrtf(__ldg(v2 + t) + EPS_BN);
        sh_t2[t] = __ldg(b2 + t) * s2 + __ldg(be2 + t) - __ldg(m2 + t) * s2;
        sh_w3[t] = __ldg(w3 + t);
    }
    if (t == 0) sh_b3[0] = __ldg(b3);
    __syncthreads();   // last CTA-wide barrier; pipes now independent

    if (!active) return;   // idle pipes exit (after both CTA-wide barriers)

    // acc[c][pi]: channels cg*8+c, patch pi*8+pbase, k-pair packed (complete
    // per-warp conv sums — warp covers all rows, no cross-warp reduction)
    u64 acc[8][4];
#pragma unroll
    for (int c = 0; c < 8; c++)
#pragma unroll
        for (int pi = 0; pi < 4; pi++) acc[c][pi] = 0ull;

    for (int g = 0; g < NSTAGES; g++) {
        // producer: warp 0 gates reuse on empty barrier; lane 0 issues (3-ahead)
        if (cg == 0) {
            int gi = g + 3;
            if (gi < NSTAGES) {
                if (gi >= NBUF)   // buffer (gi&3) last consumed at stage gi-4 = g-1
                    mbar_wait_rlx(mbe0 + (gi & 3) * 8, ((gi >> 2) - 1) & 1);
                if (lane == 0)
                    issue_stage(xs0 + (gi & 3) * STAGE_B, gin, gi, mbf0 + (gi & 3) * 8);
            }
        }

        mbar_wait_acq(mbf0 + (g & 3) * 8, (g >> 2) & 1);

        const char* xb = xpb + (g & 3) * STAGE_B;

#pragma unroll
        for (int r = 0; r < 2; r++) {
            const char* xp = xb + r * 2048 + xoff;
            ulonglong2 xv[4];
#pragma unroll
            for (int pi = 0; pi < 4; pi++)
                xv[pi] = *(const ulonglong2*)(xp + pi * 512);

            const int kqg = (g * 2 + r) * 4 + dxq;   // 0..191
            const ulonglong2* wp = (const ulonglong2*)(wsm + kqg * 36 + cg * 8);
#pragma unroll
            for (int j = 0; j < 4; j++) {
                ulonglong2 a = wp[j];       // ch 2j,2j+1 : k = dxq*4 + 0,1
                ulonglong2 b = wp[j + 8];   // ch 2j,2j+1 : k = dxq*4 + 2,3
#pragma unroll
                for (int pi = 0; pi < 4; pi++) ffma2(acc[2 * j][pi],     xv[pi].x, a.x);
#pragma unroll
                for (int pi = 0; pi < 4; pi++) ffma2(acc[2 * j + 1][pi], xv[pi].x, a.y);
#pragma unroll
                for (int pi = 0; pi < 4; pi++) ffma2(acc[2 * j][pi],     xv[pi].y, b.x);
#pragma unroll
                for (int pi = 0; pi < 4; pi++) ffma2(acc[2 * j + 1][pi], xv[pi].y, b.y);
            }
        }

        __syncwarp();
        if (lane == 0) mbar_arrive(mbe0 + (g & 3) * 8);
    }

    // ---- epilogue (once per pipe): dx-quad reduce -> BN+ReLU -> funnel -> store ----
#pragma unroll
    for (int c = 0; c < 8; c++)
#pragma unroll
        for (int pi = 0; pi < 4; pi++) {
            acc[c][pi] = add2(acc[c][pi], __shfl_xor_sync(0xffffffffu, acc[c][pi], 1));
            acc[c][pi] = add2(acc[c][pi], __shfl_xor_sync(0xffffffffu, acc[c][pi], 2));
        }
    if (dxq == 0) {
#pragma unroll
        for (int c = 0; c < 8; c++) {
            int chn = cg * 8 + c;
            float tb = sh_t1[chn];
#pragma unroll
            for (int pi = 0; pi < 4; pi++)
                r1[(pi * 8 + pbase) * 16 + chn] = fmaxf(hsum2(acc[c][pi]) + tb, 0.0f);
        }
    }
    barp(barid);

    // 16->4->1 funnel (warp 0 of the pipe; lane = patch)
    if (tl < 32) {
        float rv[16];
        const float4* rp = (const float4*)(r1 + tl * 16);
#pragma unroll
        for (int j = 0; j < 4; j++) ((float4*)rv)[j] = rp[j];
        float z0 = sh_t2[0], z1 = sh_t2[1], z2 = sh_t2[2], z3 = sh_t2[3];
#pragma unroll
        for (int c = 0; c < 16; c++) {
            z0 = fmaf(rv[c], sh_w2[c],      z0);
            z1 = fmaf(rv[c], sh_w2[16 + c], z1);
            z2 = fmaf(rv[c], sh_w2[32 + c], z2);
            z3 = fmaf(rv[c], sh_w2[48 + c], z3);
        }
        float o = sh_b3[0];
        o = fmaf(fmaxf(z0, 0.f), sh_w3[0], o);
        o = fmaf(fmaxf(z1, 0.f), sh_w3[1], o);
        o = fmaf(fmaxf(z2, 0.f), sh_w3[2], o);
        o = fmaf(fmaxf(z3, 0.f), sh_w3[3], o);
        res[tl] = o;
    }
    barp(barid);

    // build one upsampled 2KB row; 64 threads x 2 float4
#pragma unroll
    for (int i = 0; i < 2; i++) {
        int idx = i * 64 + tl;            // 0..127
        float v = res[idx >> 2];
        ((float4*)rowb)[idx] = make_float4(v, v, v, v);
    }
    asm volatile("fence.proxy.async.shared::cta;" ::: "memory");
    barp(barid);

    if (tl == 0) {
        float* gout = out + (size_t)(P >> 5) * 262144 + (size_t)(P & 31) * 8192;
        unsigned rsrc = sbase + OFF_ROW + pipe * 2048;
#pragma unroll
        for (int row = 0; row < 16; row++)
            bulk_s2g(gout + row * 512, rsrc, 2048u);
        asm volatile("cp.async.bulk.commit_group;" ::: "memory");
        asm volatile("cp.async.bulk.wait_group 0;" ::: "memory");
    }
}

extern "C" void kernel_launch(void* const* d_in, const int* in_sizes, int n_in,
                              void* d_out, int out_size) {
    (void)in_sizes; (void)n_in; (void)out_size;
    cudaFuncSetAttribute(cnn_kernel, cudaFuncAttributeMaxDynamicSharedMemorySize, SMEM_BYTES);
    cnn_kernel<<<NSM, 512, SMEM_BYTES>>>(
        (const float*)d_in[0], (float*)d_out,
        (const float*)d_in[1],  (const float*)d_in[2],  (const float*)d_in[3],
        (const float*)d_in[4],  (const float*)d_in[5],  (const float*)d_in[6],
        (const float*)d_in[7],  (const float*)d_in[8],  (const float*)d_in[9],
        (const float*)d_in[10], (const float*)d_in[11], (const float*)d_in[12],
        (const float*)d_in[13], (const float*)d_in[14]);
}

// round 15
// speedup vs baseline: 1.0513x; 1.0513x over previous
#include <cuda_runtime.h>
#include <cstdint>

#define EPS_BN 1e-5f
typedef unsigned long long u64;

static constexpr int NSM     = 148;
static constexpr int NPIPE   = 8;      // independent 64-thread pipelines per CTA
static constexpr int NBUF    = 2;
static constexpr int STAGE_B = 6144;   // 3 rows x 2048 B
static constexpr int NSTAGES = 16;     // 48 rows / 3

// ---------------- smem map (bytes) ----------------
static constexpr int OFF_W    = 0;        // 192 kq * 36 u64 = 55296
static constexpr int OFF_X    = 55296;    // 8 pipes * 2 bufs * 6144 = 98304
static constexpr int OFF_R1   = 153600;   // 8 * 512 f = 16384
static constexpr int OFF_RES  = 169984;   // 8 * 32 f = 1024
static constexpr int OFF_ROW  = 171008;   // 8 * 512 f = 16384
static constexpr int OFF_MBF  = 187392;   // 8 pipes * 2 = 128
static constexpr int OFF_MBE  = 187520;   // 128
static constexpr int OFF_T1   = 187648;
static constexpr int OFF_W2   = 187712;
static constexpr int OFF_T2   = 187968;
static constexpr int OFF_W3   = 187984;
static constexpr int OFF_B3   = 188000;
static constexpr int SMEM_BYTES = 188032;

// ---------------- helpers ----------------
__device__ __forceinline__ u64 pack2(float a, float b) {
    return ((u64)__float_as_uint(b) << 32) | (u64)__float_as_uint(a);
}
__device__ __forceinline__ void ffma2(u64& a, u64 x, u64 w) {
    asm("fma.rn.f32x2 %0, %1, %2, %0;" : "+l"(a) : "l"(x), "l"(w));
}
__device__ __forceinline__ u64 add2(u64 a, u64 b) {
    u64 r;
    asm("add.rn.f32x2 %0, %1, %2;" : "=l"(r) : "l"(a), "l"(b));
    return r;
}
__device__ __forceinline__ float hsum2(u64 a) {
    unsigned lo, hi;
    asm("mov.b64 {%0,%1}, %2;" : "=r"(lo), "=r"(hi) : "l"(a));
    return __uint_as_float(lo) + __uint_as_float(hi);
}
__device__ __forceinline__ void mbar_init(unsigned mb, unsigned cnt) {
    asm volatile("mbarrier.init.shared.b64 [%0], %1;" :: "r"(mb), "r"(cnt) : "memory");
}
__device__ __forceinline__ void mbar_wait_acq(unsigned mb, unsigned phase) {
    asm volatile(
        "{\n\t.reg .pred P;\n"
        "W%=:\n\t"
        "mbarrier.try_wait.parity.acquire.cta.shared::cta.b64 P, [%0], %1, 0x989680;\n\t"
        "@P bra D%=;\n\t"
        "bra W%=;\n"
        "D%=:\n\t}"
        :: "r"(mb), "r"(phase) : "memory");
}
__device__ __forceinline__ void mbar_wait_rlx(unsigned mb, unsigned phase) {
    asm volatile(
        "{\n\t.reg .pred P;\n"
        "W%=:\n\t"
        "mbarrier.try_wait.parity.relaxed.cta.shared::cta.b64 P, [%0], %1, 0x989680;\n\t"
        "@P bra D%=;\n\t"
        "bra W%=;\n"
        "D%=:\n\t}"
        :: "r"(mb), "r"(phase) : "memory");
}
__device__ __forceinline__ void mbar_arrive(unsigned mb) {
    asm volatile("mbarrier.arrive.shared.b64 _, [%0];" :: "r"(mb) : "memory");
}
__device__ __forceinline__ void barp(int id) {
    asm volatile("bar.sync %0, 64;" :: "r"(id) : "memory");
}
// one 6KB stage = 3 gmem rows of the strip
__device__ __forceinline__ void issue_stage(unsigned xs, const float* gin, int q, unsigned mb) {
    asm volatile("mbarrier.arrive.expect_tx.shared.b64 _, [%0], %1;"
                 :: "r"(mb), "r"(6144u) : "memory");
#pragma unroll
    for (int r = 0; r < 3; r++) {
        int rgg = q * 3 + r;   // 0..47
        const float* src = gin + (size_t)(rgg >> 4) * 262144 + (rgg & 15) * 512;
        asm volatile(
            "cp.async.bulk.shared::cluster.global.mbarrier::complete_tx::bytes [%0], [%1], %2, [%3];"
            :: "r"(xs + r * 2048), "l"(src), "r"(2048u), "r"(mb) : "memory");
    }
}
__device__ __forceinline__ void bulk_s2g(void* gdst, unsigned ssrc, unsigned bytes) {
    asm volatile("cp.async.bulk.global.shared::cta.bulk_group [%0], [%1], %2;"
                 :: "l"(gdst), "r"(ssrc), "r"(bytes) : "memory");
}

__global__ void __launch_bounds__(512, 1)
cnn_kernel(const float* __restrict__ in, float* __restrict__ out,
           const float* __restrict__ w1, const float* __restrict__ b1,
           const float* __restrict__ g1, const float* __restrict__ be1,
           const float* __restrict__ m1, const float* __restrict__ v1,
           const float* __restrict__ w2, const float* __restrict__ b2,
           const float* __restrict__ g2, const float* __restrict__ be2,
           const float* __restrict__ m2, const float* __restrict__ v2,
           const float* __restrict__ w3, const float* __restrict__ b3) {
    extern __shared__ char smem[];
    const unsigned sbase = (unsigned)__cvta_generic_to_shared(smem);

    const int t     = threadIdx.x;
    const int pipe  = t >> 6;          // 0..7, independent 64-thread pipeline
    const int tl    = t & 63;
    const int cg    = tl >> 5;         // warp in pipe = channel group (8 ch)
    const int lane  = t & 31;
    const int dxq   = lane & 3;
    const int pbase = lane >> 2;       // 0..7
    const int xoff  = pbase * 64 + dxq * 16;
    const int barid = 1 + pipe;

    u64*   wsm   = (u64*)(smem + OFF_W);
    float* r1    = (float*)(smem + OFF_R1)  + pipe * 512;
    float* res   = (float*)(smem + OFF_RES) + pipe * 32;
    float* rowb  = (float*)(smem + OFF_ROW) + pipe * 512;
    float* sh_t1 = (float*)(smem + OFF_T1);
    float* sh_w2 = (float*)(smem + OFF_W2);
    float* sh_t2 = (float*)(smem + OFF_T2);
    float* sh_w3 = (float*)(smem + OFF_W3);
    float* sh_b3 = (float*)(smem + OFF_B3);
    const unsigned mbf0 = sbase + OFF_MBF + pipe * NBUF * 8;
    const unsigned mbe0 = sbase + OFF_MBE + pipe * NBUF * 8;
    const unsigned xs0  = sbase + OFF_X + pipe * (NBUF * STAGE_B);

    const int P = blockIdx.x + NSM * pipe;   // strip id; 1184 pipes >= 1024 strips
    const bool active = (P < 1024);

    if (t == 0) {
#pragma unroll
        for (int i = 0; i < NPIPE * NBUF; i++) {
            mbar_init(sbase + OFF_MBF + i * 8, 1);
            mbar_init(sbase + OFF_MBE + i * 8, 2);   // one arrive per warp
        }
    }
    __syncthreads();

    const float* gin = in + (size_t)(P >> 5) * 786432 + (size_t)(P & 31) * 8192;
    if (active && tl == 0)
        issue_stage(xs0, gin, 0, mbf0);   // prologue: stage 0 into buf 0

    // ---- fold BN1 into conv1 weights (hides prefetch latency) ----
#pragma unroll
    for (int j = 0; j < 6; j++) {
        int idx = j * 512 + t;          // 0..3071
        int c = idx & 15, kq = idx >> 4;
        float s1 = __ldg(g1 + c) * rsqrtf(__ldg(v1 + c) + EPS_BN);
        float4 w = *(const float4*)(w1 + c * 768 + kq * 4);
        wsm[kq * 36 + c]      = pack2(w.x * s1, w.y * s1);
        wsm[kq * 36 + 16 + c] = pack2(w.z * s1, w.w * s1);
    }
    if (t < 16) {
        float s1 = __ldg(g1 + t) * rsqrtf(__ldg(v1 + t) + EPS_BN);
        sh_t1[t] = __ldg(b1 + t) * s1 + __ldg(be1 + t) - __ldg(m1 + t) * s1;
    }
    if (t < 64) {
        int o = t >> 4;
        float s2 = __ldg(g2 + o) * rsqrtf(__ldg(v2 + o) + EPS_BN);
        sh_w2[t] = __ldg(w2 + t) * s2;
    }
    if (t < 4) {
        float s2 = __ldg(g2 + t) * rsqrtf(__ldg(v2 + t) + EPS_BN);
        sh_t2[t] = __ldg(b2 + t) * s2 + __ldg(be2 + t) - __ldg(m2 + t) * s2;
        sh_w3[t] = __ldg(w3 + t);
    }
    if (t == 0) sh_b3[0] = __ldg(b3);
    __syncthreads();   // last CTA-wide barrier; pipes now independent

    if (!active) return;   // idle pipes exit (after both CTA-wide barriers)

    // acc[c][pi]: channels cg*8+c, patch pi*8+pbase, k-pair packed (complete
    // per-warp conv sums — warp covers all rows, no cross-warp reduction)
    u64 acc[8][4];
#pragma unroll
    for (int c = 0; c < 8; c++)
#pragma unroll
        for (int pi = 0; pi < 4; pi++) acc[c][pi] = 0ull;

    // strength-reduced bases: all inner offsets become compile-time immediates
    const u64*  wbase0 = wsm + dxq * 36 + cg * 8;     // advances 12*36 u64 per stage
    const char* xb0    = smem + OFF_X + pipe * (NBUF * STAGE_B) + xoff;

    // 4x-unrolled stage loop: gb multiple of 4 -> (g&1) and both mbar phases
    // are literals inside each sub-body (zero per-stage index ALU).
#pragma unroll 1
    for (int gb = 0; gb < NSTAGES; gb += 4) {
        const u64* wgb = wbase0 + (size_t)gb * 12 * 36;
        const unsigned phase01 = (unsigned)((gb >> 1) & 1);   // 0 (gb mult of 4)
        (void)phase01;

#pragma unroll
        for (int u = 0; u < 4; u++) {
            const int g = gb + u;
            const int buf = u & 1;                       // literal
            const unsigned phc = (u >> 1) & 1;           // consumer phase (gb/2 even)

            // producer: warp 0 gates reuse on empty barrier; lane 0 issues (1-ahead)
            if (cg == 0) {
                const int gi = g + 1;
                if (gi < NSTAGES) {
                    const int bufi = (u + 1) & 1;            // literal
                    const unsigned phe = ((((u + 1) >> 1) & 1) ^ 1u);  // ((gi>>1)-1)&1
                    if (gi >= NBUF)
                        mbar_wait_rlx(mbe0 + bufi * 8, phe);
                    if (lane == 0)
                        issue_stage(xs0 + bufi * STAGE_B, gin, gi, mbf0 + bufi * 8);
                }
            }

            mbar_wait_acq(mbf0 + buf * 8, phc);

            const char* xb = xb0 + buf * STAGE_B;
            const u64*  wg = wgb + u * 12 * 36;

#pragma unroll
            for (int r = 0; r < 3; r++) {
                const char* xp = xb + r * 2048;
                ulonglong2 xv[4];
#pragma unroll
                for (int pi = 0; pi < 4; pi++)
                    xv[pi] = *(const ulonglong2*)(xp + pi * 512);

                const ulonglong2* wp = (const ulonglong2*)(wg + r * 4 * 36);
#pragma unroll
                for (int j = 0; j < 4; j++) {
                    ulonglong2 a = wp[j];       // ch 2j,2j+1 : k = dxq*4 + 0,1
                    ulonglong2 b = wp[j + 8];   // ch 2j,2j+1 : k = dxq*4 + 2,3
#pragma unroll
                    for (int pi = 0; pi < 4; pi++) ffma2(acc[2 * j][pi],     xv[pi].x, a.x);
#pragma unroll
                    for (int pi = 0; pi < 4; pi++) ffma2(acc[2 * j + 1][pi], xv[pi].x, a.y);
#pragma unroll
                    for (int pi = 0; pi < 4; pi++) ffma2(acc[2 * j][pi],     xv[pi].y, b.x);
#pragma unroll
                    for (int pi = 0; pi < 4; pi++) ffma2(acc[2 * j + 1][pi], xv[pi].y, b.y);
                }
            }

            __syncwarp();
            if (lane == 0) mbar_arrive(mbe0 + buf * 8);
        }
    }

    // ---- epilogue (once per pipe): dx-quad reduce -> BN+ReLU -> funnel -> store ----
#pragma unroll
    for (int c = 0; c < 8; c++)
#pragma unroll
        for (int pi = 0; pi < 4; pi++) {
            acc[c][pi] = add2(acc[c][pi], __shfl_xor_sync(0xffffffffu, acc[c][pi], 1));
            acc[c][pi] = add2(acc[c][pi], __shfl_xor_sync(0xffffffffu, acc[c][pi], 2));
        }
    if (dxq == 0) {
#pragma unroll
        for (int c = 0; c < 8; c++) {
            int chn = cg * 8 + c;
            float tb = sh_t1[chn];
#pragma unroll
            for (int pi = 0; pi < 4; pi++)
                r1[(pi * 8 + pbase) * 16 + chn] = fmaxf(hsum2(acc[c][pi]) + tb, 0.0f);
        }
    }
    barp(barid);

    // 16->4->1 funnel (warp 0 of the pipe; lane = patch)
    if (tl < 32) {
        float rv[16];
        const float4* rp = (const float4*)(r1 + tl * 16);
#pragma unroll
        for (int j = 0; j < 4; j++) ((float4*)rv)[j] = rp[j];
        float z0 = sh_t2[0], z1 = sh_t2[1], z2 = sh_t2[2], z3 = sh_t2[3];
#pragma unroll
        for (int c = 0; c < 16; c++) {
            z0 = fmaf(rv[c], sh_w2[c],      z0);
            z1 = fmaf(rv[c], sh_w2[16 + c], z1);
            z2 = fmaf(rv[c], sh_w2[32 + c], z2);
            z3 = fmaf(rv[c], sh_w2[48 + c], z3);
        }
        float o = sh_b3[0];
        o = fmaf(fmaxf(z0, 0.f), sh_w3[0], o);
        o = fmaf(fmaxf(z1, 0.f), sh_w3[1], o);
        o = fmaf(fmaxf(z2, 0.f), sh_w3[2], o);
        o = fmaf(fmaxf(z3, 0.f), sh_w3[3], o);
        res[tl] = o;
    }
    barp(barid);

    // build one upsampled 2KB row; 64 threads x 2 float4
#pragma unroll
    for (int i = 0; i < 2; i++) {
        int idx = i * 64 + tl;            // 0..127
        float v = res[idx >> 2];
        ((float4*)rowb)[idx] = make_float4(v, v, v, v);
    }
    asm volatile("fence.proxy.async.shared::cta;" ::: "memory");
    barp(barid);

    if (tl == 0) {
        float* gout = out + (size_t)(P >> 5) * 262144 + (size_t)(P & 31) * 8192;
        unsigned rsrc = sbase + OFF_ROW + pipe * 2048;
#pragma unroll
        for (int row = 0; row < 16; row++)
            bulk_s2g(gout + row * 512, rsrc, 2048u);
        asm volatile("cp.async.bulk.commit_group;" ::: "memory");
        asm volatile("cp.async.bulk.wait_group 0;" ::: "memory");
    }
}

extern "C" void kernel_launch(void* const* d_in, const int* in_sizes, int n_in,
                              void* d_out, int out_size) {
    (void)in_sizes; (void)n_in; (void)out_size;
    cudaFuncSetAttribute(cnn_kernel, cudaFuncAttributeMaxDynamicSharedMemorySize, SMEM_BYTES);
    cnn_kernel<<<NSM, 512, SMEM_BYTES>>>(
        (const float*)d_in[0], (float*)d_out,
        (const float*)d_in[1],  (const float*)d_in[2],  (const float*)d_in[3],
        (const float*)d_in[4],  (const float*)d_in[5],  (const float*)d_in[6],
        (const float*)d_in[7],  (const float*)d_in[8],  (const float*)d_in[9],
        (const float*)d_in[10], (const float*)d_in[11], (const float*)d_in[12],
        (const float*)d_in[13], (const float*)d_in[14]);
}